// round 1
// baseline (speedup 1.0000x reference)
#include <cuda_runtime.h>
#include <math.h>

// Problem constants
#define Bv   16
#define Cv   64
#define Hv   256
#define Wv   256
#define Kv   7
#define HIDv 16
#define NCH  (Bv * Cv)          // 1024 channels
#define HWv  (Hv * Wv)          // 65536
#define KK   (Kv * Kv)          // 49
#define COLS (Cv * KK)          // 3136

// Scratch (no cudaMalloc allowed)
__device__ float g_pooled[NCH];          // [b*64 + c]
__device__ float g_wbuf[NCH * KK];       // [(b*64+c)*49 + k]

// ---------------------------------------------------------------------------
// Kernel 1: global average pool. One block per channel.
// ---------------------------------------------------------------------------
__global__ void gap_kernel(const float* __restrict__ x) {
    const int ch = blockIdx.x;
    const float4* p = reinterpret_cast<const float4*>(x + (size_t)ch * HWv);
    float s = 0.f;
    for (int i = threadIdx.x; i < HWv / 4; i += 256) {
        float4 v = p[i];
        s += (v.x + v.y) + (v.z + v.w);
    }
    // warp reduce
    #pragma unroll
    for (int off = 16; off > 0; off >>= 1)
        s += __shfl_xor_sync(0xffffffffu, s, off);
    __shared__ float red[8];
    const int lane = threadIdx.x & 31, wid = threadIdx.x >> 5;
    if (lane == 0) red[wid] = s;
    __syncthreads();
    if (threadIdx.x == 0) {
        float t = 0.f;
        #pragma unroll
        for (int i = 0; i < 8; ++i) t += red[i];
        g_pooled[ch] = t * (1.0f / (float)HWv);
    }
}

// ---------------------------------------------------------------------------
// Kernel 2: MLP weight generator.
// Each block redundantly computes hdn[16][16] (cheap), then its slice of
// the 16x3136 second matmul + sigmoid. grid = 64 blocks, 3136/64 = 49 cols each.
// ---------------------------------------------------------------------------
__global__ void mlp_kernel(const float* __restrict__ w1, const float* __restrict__ b1,
                           const float* __restrict__ w2, const float* __restrict__ b2) {
    __shared__ float sp[NCH];       // pooled [16][64]
    __shared__ float sh[Bv * HIDv]; // hdn [16][16]
    const int tid = threadIdx.x;

    for (int i = tid; i < NCH; i += 256) sp[i] = g_pooled[i];
    __syncthreads();

    {   // one thread per hdn element (256 == 16*16)
        const int b = tid >> 4, h = tid & 15;
        float s = b1[h];
        #pragma unroll
        for (int c = 0; c < Cv; ++c)
            s = fmaf(sp[b * Cv + c], w1[c * HIDv + h], s);
        // exact GELU
        sh[tid] = 0.5f * s * (1.0f + erff(s * 0.70710678118654752f));
    }
    __syncthreads();

    const int j0 = blockIdx.x * 49;  // 64 blocks * 49 = 3136
    for (int t = tid; t < 49 * Bv; t += 256) {
        const int jl = t / 16, b = t & 15;
        const int j = j0 + jl;
        float s = b2[j];
        #pragma unroll
        for (int h = 0; h < HIDv; ++h)
            s = fmaf(sh[b * HIDv + h], w2[h * COLS + j], s);
        // wbuf[(b*64+c)*49+k] == wbuf[b*3136 + j], j = c*49+k
        g_wbuf[b * COLS + j] = 1.0f / (1.0f + __expf(-s));
    }
}

// ---------------------------------------------------------------------------
// Kernel 3: depthwise 7x7 conv, reflect padding.
// Block: 64x64 output tile of one channel. blockDim = (64,4).
// Each thread: one output column x 16 rows, sliding-window over 22 input rows.
// Smem tile: 70 rows x 72-stride (padded), loaded with reflect indexing.
// ---------------------------------------------------------------------------
__global__ void __launch_bounds__(256, 2)
dwconv_kernel(const float* __restrict__ x, float* __restrict__ out) {
    __shared__ float tile[70 * 72];
    __shared__ float wsh[KK];

    const int ch = blockIdx.z;
    const int x0 = blockIdx.x << 6;
    const int y0 = blockIdx.y << 6;
    const int tid = threadIdx.y * 64 + threadIdx.x;

    if (tid < KK) wsh[tid] = g_wbuf[ch * KK + tid];

    const float* __restrict__ xc = x + (size_t)ch * HWv;
    for (int i = tid; i < 70 * 70; i += 256) {
        const int r = i / 70;
        const int c = i - r * 70;
        int gr = y0 - 3 + r;
        gr = gr < 0 ? -gr : (gr > 255 ? 510 - gr : gr);
        int gc = x0 - 3 + c;
        gc = gc < 0 ? -gc : (gc > 255 ? 510 - gc : gc);
        tile[r * 72 + c] = xc[gr * Wv + gc];
    }
    __syncthreads();

    float w[KK];
    #pragma unroll
    for (int k = 0; k < KK; ++k) w[k] = wsh[k];

    float acc[16];
    #pragma unroll
    for (int o = 0; o < 16; ++o) acc[o] = 0.f;

    const int tx = threadIdx.x;
    const int rbase = threadIdx.y * 16;  // first input row (in smem coords) for this thread

    #pragma unroll
    for (int r = 0; r < 22; ++r) {      // 16 output rows + 6 halo rows
        float v[7];
        const float* row = &tile[(rbase + r) * 72 + tx];
        #pragma unroll
        for (int dx = 0; dx < 7; ++dx) v[dx] = row[dx];
        #pragma unroll
        for (int o = 0; o < 16; ++o) {
            if (o <= r && r <= o + 6) {
                const int dy = r - o;
                #pragma unroll
                for (int dx = 0; dx < 7; ++dx)
                    acc[o] = fmaf(w[dy * 7 + dx], v[dx], acc[o]);
            }
        }
    }

    float* __restrict__ oc = out + (size_t)ch * HWv;
    #pragma unroll
    for (int o = 0; o < 16; ++o)
        oc[(y0 + rbase + o) * Wv + x0 + tx] = acc[o];
}

// ---------------------------------------------------------------------------
extern "C" void kernel_launch(void* const* d_in, const int* in_sizes, int n_in,
                              void* d_out, int out_size) {
    const float* x  = (const float*)d_in[0];
    const float* w1 = (const float*)d_in[1];
    const float* b1 = (const float*)d_in[2];
    const float* w2 = (const float*)d_in[3];
    const float* b2 = (const float*)d_in[4];
    float* out = (float*)d_out;

    gap_kernel<<<NCH, 256>>>(x);
    mlp_kernel<<<64, 256>>>(w1, b1, w2, b2);
    dwconv_kernel<<<dim3(4, 4, NCH), dim3(64, 4)>>>(x, out);
}